// round 7
// baseline (speedup 1.0000x reference)
#include <cuda_runtime.h>

#define BATCH  4096
#define TSTEPS 512
#define IN     3
#define HID    64
#define G      256      // 4*HID
#define NCTA   304      // 2 CTAs per SM (152 SMs)
#define NTH    256
#define MAXR   14

typedef unsigned long long ull;

// fma.rn.f32x2 on packed 64-bit registers (sm_100+): 2 fp32 FMAs / instr.
__device__ __forceinline__ ull ffma2u(ull a, ull b, ull c) {
    ull d;
    asm("fma.rn.f32x2 %0, %1, %2, %3;" : "=l"(d) : "l"(a), "l"(b), "l"(c));
    return d;
}
__device__ __forceinline__ float f2sum(ull v) {
    float lo, hi;
    asm("mov.b64 {%0, %1}, %2;" : "=f"(lo), "=f"(hi) : "l"(v));
    return lo + hi;
}

__device__ __forceinline__ float fast_rcp(float x) {
    float r;
    asm("rcp.approx.f32 %0, %1;" : "=f"(r) : "f"(x));
    return r;
}
// sigmoid: 1 EX2 + 1 RCP, rel err ~1e-6
__device__ __forceinline__ float sigmoidf_(float x) {
    return fast_rcp(1.0f + __expf(-x));
}
// tanh: 1 EX2 + 1 RCP, stable for large |x|
__device__ __forceinline__ float tanhf_(float x) {
    return 1.0f - 2.0f * fast_rcp(1.0f + __expf(2.0f * x));
}

__global__ void __launch_bounds__(NTH, 2)
lstm_fused_kernel(const float* __restrict__ x,
                  const float* __restrict__ W_ih,
                  const float* __restrict__ W_hh,
                  const float* __restrict__ b_ih,
                  const float* __restrict__ b_hh,
                  const float* __restrict__ W_dec,
                  const float* __restrict__ b_dec,
                  float* __restrict__ out)
{
    __shared__ __align__(16) float h_s[MAXR][HID];     // h_t per row
    __shared__ __align__(16) float g_s[MAXR][G];       // activated gates
    __shared__ __align__(16) float x_s[MAXR * 4];      // x_t staging (padded to 4)
    __shared__ __align__(16) float wdec_s[IN][HID];
    __shared__ float bdec_s[IN];

    const int tid = threadIdx.x;
    const int bid = blockIdx.x;

    // batch-row distribution: 4096 = 144*14 + 160*13 over 304 CTAs
    const int BASE = BATCH / NCTA;                 // 13
    const int REM  = BATCH - BASE * NCTA;          // 144
    const int rows = BASE + (bid < REM ? 1 : 0);
    const int b0   = bid * BASE + min(bid, REM);

    // --- In-warp K-split, N'=2: warp covers 32 consecutive gate columns.
    // lane l: columns {j0, j0+1}, K-half = (l>>4)*32 .. +32.
    const int warp  = tid >> 5;
    const int lane  = tid & 31;
    const int khalf = lane >> 4;             // 0 or 1
    const int lane2 = lane & 15;
    const int j0    = warp * 32 + lane2 * 2; // even column
    const bool gate_tanh = ((warp >> 1) == 2);   // cols [128,192) -> g gate -> tanh

    // Resident weights: 2 columns x K-half(32) = 64 fp32 = 32 ull regs.
    ull wA[16], wB[16];
    {
        const ulonglong2* pA =
            reinterpret_cast<const ulonglong2*>(W_hh + j0 * HID + khalf * 32);
        const ulonglong2* pB =
            reinterpret_cast<const ulonglong2*>(W_hh + (j0 + 1) * HID + khalf * 32);
        #pragma unroll
        for (int i = 0; i < 8; i++) {
            ulonglong2 vA = pA[i];
            ulonglong2 vB = pB[i];
            wA[2 * i] = vA.x;  wA[2 * i + 1] = vA.y;
            wB[2 * i] = vB.x;  wB[2 * i + 1] = vB.y;
        }
    }
    const float wia0 = W_ih[j0 * IN + 0], wia1 = W_ih[j0 * IN + 1], wia2 = W_ih[j0 * IN + 2];
    const float wib0 = W_ih[(j0 + 1) * IN + 0], wib1 = W_ih[(j0 + 1) * IN + 1],
                wib2 = W_ih[(j0 + 1) * IN + 2];
    const float bias0 = b_ih[j0] + b_hh[j0];
    const float bias1 = b_ih[j0 + 1] + b_hh[j0 + 1];

    // decode weights to smem
    if (tid < IN * HID) wdec_s[tid / HID][tid % HID] = W_dec[tid];
    if (tid < IN)       bdec_s[tid] = b_dec[tid];

    // init h = 0
    for (int i = tid; i < rows * HID; i += NTH) h_s[i >> 6][i & 63] = 0.0f;

    // per-thread cell state: one float4 group (rows*16 <= 224 <= 256 threads)
    float4 c4 = make_float4(0.f, 0.f, 0.f, 0.f);
    const bool b_valid = (tid < rows * (HID / 4));
    const int  b_r  = tid >> 4;
    const int  b_h4 = (tid & 15) * 4;

    // (r, lane) mapping for x-staging and decode: tid < rows*3 (<=42)
    const bool d_valid = (tid < rows * IN);
    const int  d_r = tid / IN;
    const int  d_o = tid - d_r * IN;
    const size_t xo_base = ((size_t)(b0 + d_r) * TSTEPS) * IN + d_o;

    if (d_valid) x_s[d_r * 4 + d_o] = x[xo_base];   // stage x for t = 0

    __syncthreads();

    for (int t = 0; t < TSTEPS; t++) {
        // ---------- Phase A: 2 columns/lane, K-half/lane, shfl-combine ----------
        for (int r = 0; r < rows; r++) {
            float4 xv = *reinterpret_cast<const float4*>(&x_s[r * 4]);
            float xa0 = fmaf(xv.z, wia2, fmaf(xv.y, wia1, fmaf(xv.x, wia0, bias0)));
            float xa1 = fmaf(xv.z, wib2, fmaf(xv.y, wib1, fmaf(xv.x, wib0, bias1)));

            const ulonglong2* hp =
                reinterpret_cast<const ulonglong2*>(h_s[r] + khalf * 32);
            ull a00 = 0, a01 = 0, a10 = 0, a11 = 0;   // 4 independent chains
            #pragma unroll
            for (int i = 0; i < 8; i++) {             // 8 x 16B = 32-float K-half
                ulonglong2 hv = hp[i];
                a00 = ffma2u(hv.x, wA[2 * i],     a00);
                a10 = ffma2u(hv.x, wB[2 * i],     a10);
                a01 = ffma2u(hv.y, wA[2 * i + 1], a01);
                a11 = ffma2u(hv.y, wB[2 * i + 1], a11);
            }
            float p0 = f2sum(a00) + f2sum(a01);       // partial (this K-half), col j0
            float p1 = f2sum(a10) + f2sum(a11);       // partial, col j0+1
            p0 += __shfl_xor_sync(0xffffffffu, p0, 16);
            p1 += __shfl_xor_sync(0xffffffffu, p1, 16);
            float g0 = xa0 + p0;
            float g1 = xa1 + p1;
            float act0 = gate_tanh ? tanhf_(g0) : sigmoidf_(g0);
            float act1 = gate_tanh ? tanhf_(g1) : sigmoidf_(g1);
            if (lane < 16)
                *reinterpret_cast<float2*>(&g_s[r][j0]) = make_float2(act0, act1);
        }
        __syncthreads();   // gates ready

        // ---------- Phase B: c_t = f*c + i*g ; h_t = o*tanh(c_t) ----------
        if (b_valid) {
            float4 ig = *reinterpret_cast<const float4*>(&g_s[b_r][b_h4]);
            float4 fg = *reinterpret_cast<const float4*>(&g_s[b_r][HID + b_h4]);
            float4 gg = *reinterpret_cast<const float4*>(&g_s[b_r][2 * HID + b_h4]);
            float4 og = *reinterpret_cast<const float4*>(&g_s[b_r][3 * HID + b_h4]);
            float4 cn;
            cn.x = fmaf(fg.x, c4.x, ig.x * gg.x);
            cn.y = fmaf(fg.y, c4.y, ig.y * gg.y);
            cn.z = fmaf(fg.z, c4.z, ig.z * gg.z);
            cn.w = fmaf(fg.w, c4.w, ig.w * gg.w);
            c4 = cn;
            float4 hn;
            hn.x = og.x * tanhf_(cn.x);
            hn.y = og.y * tanhf_(cn.y);
            hn.z = og.z * tanhf_(cn.z);
            hn.w = og.w * tanhf_(cn.w);
            *reinterpret_cast<float4*>(&h_s[b_r][b_h4]) = hn;
        }
        // prefetch x for t+1 (readers wait at the barrier below)
        if (d_valid && (t + 1) < TSTEPS)
            x_s[d_r * 4 + d_o] = x[xo_base + (size_t)(t + 1) * IN];
        __syncthreads();   // h_t ready

        // ---------- Phase C: out[b, t, o] = b_dec[o] + h_t · W_dec[o] ----------
        if (d_valid) {
            const ulonglong2* hp = reinterpret_cast<const ulonglong2*>(h_s[d_r]);
            const ulonglong2* wp = reinterpret_cast<const ulonglong2*>(wdec_s[d_o]);
            ull a0 = 0, a1 = 0;
            #pragma unroll
            for (int i = 0; i < 16; i++) {
                ulonglong2 hv = hp[i];
                ulonglong2 wv = wp[i];
                a0 = ffma2u(hv.x, wv.x, a0);
                a1 = ffma2u(hv.y, wv.y, a1);
            }
            out[xo_base + (size_t)t * IN] = bdec_s[d_o] + f2sum(a0) + f2sum(a1);
        }
        // Phase C only reads h_s; next write to h_s (Phase B) is after a barrier.
    }
}

extern "C" void kernel_launch(void* const* d_in, const int* in_sizes, int n_in,
                              void* d_out, int out_size)
{
    (void)in_sizes; (void)n_in; (void)out_size;
    const float* x     = (const float*)d_in[0];
    const float* W_ih  = (const float*)d_in[1];
    const float* W_hh  = (const float*)d_in[2];
    const float* b_ih  = (const float*)d_in[3];
    const float* b_hh  = (const float*)d_in[4];
    const float* W_dec = (const float*)d_in[5];
    const float* b_dec = (const float*)d_in[6];
    float* out = (float*)d_out;

    lstm_fused_kernel<<<NCTA, NTH>>>(x, W_ih, W_hh, b_ih, b_hh, W_dec, b_dec, out);
}

// round 8
// speedup vs baseline: 1.0013x; 1.0013x over previous
#include <cuda_runtime.h>

#define BATCH  4096
#define TSTEPS 512
#define IN     3
#define HID    64
#define G      256      // 4*HID
#define NCTA   304      // 2 CTAs per SM (152 SMs)
#define NTH    256
#define MAXR   14
#define HPAD   68       // h_s row stride (float): 272B -> 4-bank shift per row
#define GPAD   260      // g_s row stride (float): 1040B -> 4-bank shift per row

typedef unsigned long long ull;

// fma.rn.f32x2 on packed 64-bit registers (sm_100+): 2 fp32 FMAs / instr.
__device__ __forceinline__ ull ffma2u(ull a, ull b, ull c) {
    ull d;
    asm("fma.rn.f32x2 %0, %1, %2, %3;" : "=l"(d) : "l"(a), "l"(b), "l"(c));
    return d;
}
__device__ __forceinline__ ull addf32x2(ull a, ull b) {
    ull d;
    asm("add.rn.f32x2 %0, %1, %2;" : "=l"(d) : "l"(a), "l"(b));
    return d;
}
__device__ __forceinline__ float f2sum(ull v) {
    float lo, hi;
    asm("mov.b64 {%0, %1}, %2;" : "=f"(lo), "=f"(hi) : "l"(v));
    return lo + hi;
}

__device__ __forceinline__ float fast_rcp(float x) {
    float r;
    asm("rcp.approx.f32 %0, %1;" : "=f"(r) : "f"(x));
    return r;
}
// sigmoid: 1 EX2 + 1 RCP, rel err ~1e-6
__device__ __forceinline__ float sigmoidf_(float x) {
    return fast_rcp(1.0f + __expf(-x));
}
// tanh: 1 EX2 + 1 RCP, stable for large |x|
__device__ __forceinline__ float tanhf_(float x) {
    return 1.0f - 2.0f * fast_rcp(1.0f + __expf(2.0f * x));
}

__global__ void __launch_bounds__(NTH, 2)
lstm_fused_kernel(const float* __restrict__ x,
                  const float* __restrict__ W_ih,
                  const float* __restrict__ W_hh,
                  const float* __restrict__ b_ih,
                  const float* __restrict__ b_hh,
                  const float* __restrict__ W_dec,
                  const float* __restrict__ b_dec,
                  float* __restrict__ out)
{
    __shared__ __align__(16) float h_s[MAXR][HPAD];    // h_t per row (padded)
    __shared__ __align__(16) float g_s[MAXR][GPAD];    // activated gates (padded)
    __shared__ __align__(16) float x_s[MAXR * 4];      // x_t staging (padded to 4)
    __shared__ __align__(16) float wdec_s[IN][HID];
    __shared__ float bdec_s[IN];

    const int tid = threadIdx.x;
    const int bid = blockIdx.x;

    // batch-row distribution: 4096 = 144*14 + 160*13 over 304 CTAs
    const int BASE = BATCH / NCTA;                 // 13
    const int REM  = BATCH - BASE * NCTA;          // 144
    const int rows = BASE + (bid < REM ? 1 : 0);
    const int b0   = bid * BASE + min(bid, REM);

    // --- In-warp K-split (interleaved 16B chunks), N'=2.
    // lane l: columns {j0, j0+1}; K chunks {2i + khalf}, i=0..7 (4 floats each).
    // The two addresses of one LDS.128 are ADJACENT 16B chunks -> no bank conflict.
    const int warp  = tid >> 5;
    const int lane  = tid & 31;
    const int khalf = lane >> 4;             // 0 or 1
    const int lane2 = lane & 15;
    const int j0    = warp * 32 + lane2 * 2; // even column
    const bool gate_tanh = ((warp >> 1) == 2);   // cols [128,192) -> g gate -> tanh

    // Resident weights: 2 columns x 32 K-floats (chunks 2i+khalf) = 32 ull regs.
    ull wA[16], wB[16];
    {
        #pragma unroll
        for (int i = 0; i < 8; i++) {
            const int c = 2 * i + khalf;     // 16B chunk index within the 64-float row
            ulonglong2 vA = *reinterpret_cast<const ulonglong2*>(W_hh + j0 * HID + c * 4);
            ulonglong2 vB = *reinterpret_cast<const ulonglong2*>(W_hh + (j0 + 1) * HID + c * 4);
            wA[2 * i] = vA.x;  wA[2 * i + 1] = vA.y;
            wB[2 * i] = vB.x;  wB[2 * i + 1] = vB.y;
        }
    }
    const float wia0 = W_ih[j0 * IN + 0], wia1 = W_ih[j0 * IN + 1], wia2 = W_ih[j0 * IN + 2];
    const float wib0 = W_ih[(j0 + 1) * IN + 0], wib1 = W_ih[(j0 + 1) * IN + 1],
                wib2 = W_ih[(j0 + 1) * IN + 2];
    const float bias0 = b_ih[j0] + b_hh[j0];
    const float bias1 = b_ih[j0 + 1] + b_hh[j0 + 1];

    // decode weights to smem
    if (tid < IN * HID) wdec_s[tid / HID][tid % HID] = W_dec[tid];
    if (tid < IN)       bdec_s[tid] = b_dec[tid];

    // init h = 0
    for (int i = tid; i < rows * HID; i += NTH) h_s[i >> 6][i & 63] = 0.0f;

    // per-thread cell state: one float4 group (rows*16 <= 224 <= 256 threads)
    float4 c4 = make_float4(0.f, 0.f, 0.f, 0.f);
    const bool b_valid = (tid < rows * (HID / 4));
    const int  b_r  = tid >> 4;
    const int  b_h4 = (tid & 15) * 4;

    // (r, lane) mapping for x-staging and decode: tid < rows*3 (<=42)
    const bool d_valid = (tid < rows * IN);
    const int  d_r = tid / IN;
    const int  d_o = tid - d_r * IN;
    const size_t xo_base = ((size_t)(b0 + d_r) * TSTEPS) * IN + d_o;

    if (d_valid) x_s[d_r * 4 + d_o] = x[xo_base];   // stage x for t = 0

    __syncthreads();

    for (int t = 0; t < TSTEPS; t++) {
        // ---------- Phase A: 2 columns/lane, interleaved K-split, shfl-combine ----
        for (int r = 0; r < rows; r++) {
            float4 xv = *reinterpret_cast<const float4*>(&x_s[r * 4]);
            float xa0 = fmaf(xv.z, wia2, fmaf(xv.y, wia1, fmaf(xv.x, wia0, bias0)));
            float xa1 = fmaf(xv.z, wib2, fmaf(xv.y, wib1, fmaf(xv.x, wib0, bias1)));

            const ulonglong2* hp = reinterpret_cast<const ulonglong2*>(h_s[r]);
            ull a00 = 0, a01 = 0, a10 = 0, a11 = 0;   // 4 independent chains
            #pragma unroll
            for (int i = 0; i < 8; i++) {             // chunk 2i+khalf (16B)
                ulonglong2 hv = hp[2 * i + khalf];
                a00 = ffma2u(hv.x, wA[2 * i],     a00);
                a10 = ffma2u(hv.x, wB[2 * i],     a10);
                a01 = ffma2u(hv.y, wA[2 * i + 1], a01);
                a11 = ffma2u(hv.y, wB[2 * i + 1], a11);
            }
            float p0 = f2sum(addf32x2(a00, a01));     // partial (this K-half), col j0
            float p1 = f2sum(addf32x2(a10, a11));     // partial, col j0+1
            p0 += __shfl_xor_sync(0xffffffffu, p0, 16);
            p1 += __shfl_xor_sync(0xffffffffu, p1, 16);
            float g0 = xa0 + p0;
            float g1 = xa1 + p1;
            float act0 = gate_tanh ? tanhf_(g0) : sigmoidf_(g0);
            float act1 = gate_tanh ? tanhf_(g1) : sigmoidf_(g1);
            if (lane < 16)
                *reinterpret_cast<float2*>(&g_s[r][j0]) = make_float2(act0, act1);
        }
        __syncthreads();   // gates ready

        // ---------- Phase B: c_t = f*c + i*g ; h_t = o*tanh(c_t) ----------
        if (b_valid) {
            float4 ig = *reinterpret_cast<const float4*>(&g_s[b_r][b_h4]);
            float4 fg = *reinterpret_cast<const float4*>(&g_s[b_r][HID + b_h4]);
            float4 gg = *reinterpret_cast<const float4*>(&g_s[b_r][2 * HID + b_h4]);
            float4 og = *reinterpret_cast<const float4*>(&g_s[b_r][3 * HID + b_h4]);
            float4 cn;
            cn.x = fmaf(fg.x, c4.x, ig.x * gg.x);
            cn.y = fmaf(fg.y, c4.y, ig.y * gg.y);
            cn.z = fmaf(fg.z, c4.z, ig.z * gg.z);
            cn.w = fmaf(fg.w, c4.w, ig.w * gg.w);
            c4 = cn;
            float4 hn;
            hn.x = og.x * tanhf_(cn.x);
            hn.y = og.y * tanhf_(cn.y);
            hn.z = og.z * tanhf_(cn.z);
            hn.w = og.w * tanhf_(cn.w);
            *reinterpret_cast<float4*>(&h_s[b_r][b_h4]) = hn;
        }
        // prefetch x for t+1 (readers wait at the barrier below)
        if (d_valid && (t + 1) < TSTEPS)
            x_s[d_r * 4 + d_o] = x[xo_base + (size_t)(t + 1) * IN];
        __syncthreads();   // h_t ready

        // ---------- Phase C: out[b, t, o] = b_dec[o] + h_t · W_dec[o] ----------
        if (d_valid) {
            const ulonglong2* hp = reinterpret_cast<const ulonglong2*>(h_s[d_r]);
            const ulonglong2* wp = reinterpret_cast<const ulonglong2*>(wdec_s[d_o]);
            ull a0 = 0, a1 = 0;
            #pragma unroll
            for (int i = 0; i < 16; i++) {
                ulonglong2 hv = hp[i];
                ulonglong2 wv = wp[i];
                a0 = ffma2u(hv.x, wv.x, a0);
                a1 = ffma2u(hv.y, wv.y, a1);
            }
            out[xo_base + (size_t)t * IN] = bdec_s[d_o] + f2sum(addf32x2(a0, a1));
        }
        // Phase C only reads h_s; next write to h_s (Phase B) is after a barrier.
    }
}

extern "C" void kernel_launch(void* const* d_in, const int* in_sizes, int n_in,
                              void* d_out, int out_size)
{
    (void)in_sizes; (void)n_in; (void)out_size;
    const float* x     = (const float*)d_in[0];
    const float* W_ih  = (const float*)d_in[1];
    const float* W_hh  = (const float*)d_in[2];
    const float* b_ih  = (const float*)d_in[3];
    const float* b_hh  = (const float*)d_in[4];
    const float* W_dec = (const float*)d_in[5];
    const float* b_dec = (const float*)d_in[6];
    float* out = (float*)d_out;

    lstm_fused_kernel<<<NCTA, NTH>>>(x, W_ih, W_hh, b_ih, b_hh, W_dec, b_dec, out);
}